// round 10
// baseline (speedup 1.0000x reference)
#include <cuda_runtime.h>
#include <cstdint>

#define NB   16
#define FIN  64
#define FOUT 128
#define NP   2048
#define KNN  20
#define NPTS (NB * NP)            /* 32768 */
#define EDGES (NPTS * KNN)        /* 655360 */

typedef unsigned long long u64;

// ---------------- scratch (device globals: no allocations allowed) ----------
__device__ float g_sq[NPTS];
__device__ float g_key[(size_t)NPTS * NP];   // 256 MB
__device__ int   g_idx[NPTS * KNN];
__device__ float g_A[FIN * FOUT];            // (W1-W2)^T  [f][o]
__device__ float g_C[FIN * FOUT];            // W2^T       [f][o]
__device__ float g_P[NPTS * FOUT];
__device__ float g_Q[NPTS * FOUT];
__device__ float g_ymax[NPTS * FOUT];
__device__ float g_ymin[NPTS * FOUT];
__device__ float g_S1[FOUT];
__device__ float g_S2[FOUT];
__device__ float g_scale[FOUT];
__device__ float g_shift[FOUT];

// ---------------- f32x2 helpers (Blackwell packed fp32 FMA) -----------------
__device__ __forceinline__ u64 fma2(u64 a, u64 b, u64 c) {
    u64 d;
    asm("fma.rn.f32x2 %0, %1, %2, %3;" : "=l"(d) : "l"(a), "l"(b), "l"(c));
    return d;
}
__device__ __forceinline__ u64 dupf(float a) {
    u64 d;
    unsigned u = __float_as_uint(a);
    asm("mov.b64 %0, {%1, %1};" : "=l"(d) : "r"(u));
    return d;
}
__device__ __forceinline__ float2 unpack2(u64 d) {
    unsigned lo, hi;
    asm("mov.b64 {%0, %1}, %2;" : "=r"(lo), "=r"(hi) : "l"(d));
    return make_float2(__uint_as_float(lo), __uint_as_float(hi));
}

// ---------------- kernels ---------------------------------------------------

__global__ void k_zero() {
    int t = threadIdx.x;
    if (t < FOUT) { g_S1[t] = 0.f; g_S2[t] = 0.f; }
}

// sq[b,n] = sum_f x^2
__global__ void k_sq(const float* __restrict__ x) {
    int gp = blockIdx.x * blockDim.x + threadIdx.x;
    if (gp >= NPTS) return;
    int b = gp >> 11, n = gp & (NP - 1);
    const float* p = x + (size_t)b * FIN * NP + n;
    float s = 0.f;
#pragma unroll
    for (int f = 0; f < FIN; f++) { float v = p[(size_t)f * NP]; s = fmaf(v, v, s); }
    g_sq[gp] = s;
}

// Transpose weights: g_A[f][o] = W[o][f]-W[o][64+f], g_C[f][o] = W[o][64+f]
// Exactly FIN*FOUT = 8192 elements.
__global__ void k_prep(const float* __restrict__ W) {
    int id = blockIdx.x * 256 + threadIdx.x;   // 0..8191
    if (id >= FIN * FOUT) return;
    int f = id >> 7, o = id & 127;
    float w1 = W[o * 128 + f], w2 = W[o * 128 + 64 + f];
    g_A[f * 128 + o] = w1 - w2;
    g_C[f * 128 + o] = w2;
}

// Symmetric Gram, lower-triangle 128x128 tiles; keys are TRUE squared
// distances (>=0): key[b,n,m] = sq[n]+sq[m]-2G, so positive-float bits are
// unsigned-sortable in k_select with no transform. Plain stores (NOT __stcs):
// k_select runs immediately after and re-reads these 256 MB — L2 residency
// of the tail ~126 MB is worth >100 us there.
__global__ __launch_bounds__(256, 2) void k_gram(const float* __restrict__ x) {
    extern __shared__ float sm[];
    float* As = sm;               // [64][128]
    float* Bs = sm + 64 * 128;    // [64][128]
    int b = blockIdx.z;
    int kk = blockIdx.x;
    int ti = (int)((sqrtf(8.f * kk + 1.f) - 1.f) * 0.5f);
    while ((ti + 1) * (ti + 2) / 2 <= kk) ti++;
    while (ti * (ti + 1) / 2 > kk) ti--;
    int tj = kk - ti * (ti + 1) / 2;
    int n0 = ti * 128;            // rows
    int m0 = tj * 128;            // cols
    int tid = threadIdx.x;
    const float* xb = x + (size_t)b * FIN * NP;
#pragma unroll
    for (int i = 0; i < 8; i++) {
        int flat = (tid + 256 * i) * 4;
        int k = flat >> 7;
        int c = flat & 127;
        *(float4*)(As + k * 128 + c) = *(const float4*)(xb + (size_t)k * NP + n0 + c);
        *(float4*)(Bs + k * 128 + c) = *(const float4*)(xb + (size_t)k * NP + m0 + c);
    }
    __syncthreads();
    int tx = tid & 15, ty = tid >> 4;
    u64 acc[8][4];
#pragma unroll
    for (int i = 0; i < 8; i++)
#pragma unroll
        for (int j = 0; j < 4; j++) acc[i][j] = 0ull;

#pragma unroll 4
    for (int k = 0; k < 64; k++) {
        float4 a0 = *(float4*)(As + k * 128 + ty * 8);
        float4 a1 = *(float4*)(As + k * 128 + ty * 8 + 4);
        ulonglong2 bv0 = *(ulonglong2*)(Bs + k * 128 + tx * 8);
        ulonglong2 bv1 = *(ulonglong2*)(Bs + k * 128 + tx * 8 + 4);
        float av[8] = {a0.x, a0.y, a0.z, a0.w, a1.x, a1.y, a1.z, a1.w};
        u64 bv[4] = {bv0.x, bv0.y, bv1.x, bv1.y};
#pragma unroll
        for (int i = 0; i < 8; i++) {
            u64 ad = dupf(av[i]);
#pragma unroll
            for (int j = 0; j < 4; j++) acc[i][j] = fma2(ad, bv[j], acc[i][j]);
        }
    }
    float gf[8][8];
#pragma unroll
    for (int i = 0; i < 8; i++)
#pragma unroll
        for (int j = 0; j < 4; j++) {
            float2 p = unpack2(acc[i][j]);
            gf[i][2 * j] = p.x; gf[i][2 * j + 1] = p.y;
        }
    // direct tile: rows n0+ty*8+i, cols m0+tx*8+k
    {
        float sqm[8], sqr[8];
        *(float4*)sqm       = *(const float4*)(g_sq + b * NP + m0 + tx * 8);
        *(float4*)(sqm + 4) = *(const float4*)(g_sq + b * NP + m0 + tx * 8 + 4);
        *(float4*)sqr       = *(const float4*)(g_sq + b * NP + n0 + ty * 8);
        *(float4*)(sqr + 4) = *(const float4*)(g_sq + b * NP + n0 + ty * 8 + 4);
#pragma unroll
        for (int i = 0; i < 8; i++) {
            float v[8];
#pragma unroll
            for (int k = 0; k < 8; k++)
                v[k] = fmaxf(fmaf(gf[i][k], -2.f, sqm[k] + sqr[i]), 0.f);
            float* op = g_key + ((size_t)(b * NP + n0 + ty * 8 + i)) * NP + m0 + tx * 8;
            *(float4*)op       = *(float4*)v;
            *(float4*)(op + 4) = *(float4*)(v + 4);
        }
    }
    // transposed tile (off-diagonal only): rows m0+ty*8+r, cols n0+tx*8+c
    if (ti != tj) {
        __syncthreads();
        int s = tid;
        float* slots = sm;
#pragma unroll
        for (int k = 0; k < 8; k++)
#pragma unroll
            for (int i = 0; i < 8; i++)
                slots[s * 65 + k * 8 + ((i + s) & 7)] = gf[i][k];
        __syncthreads();
        int s2 = ((tid & 15) << 4) | (tid >> 4);
        float sqn[8], sqr[8];
        *(float4*)sqn       = *(const float4*)(g_sq + b * NP + n0 + tx * 8);
        *(float4*)(sqn + 4) = *(const float4*)(g_sq + b * NP + n0 + tx * 8 + 4);
        *(float4*)sqr       = *(const float4*)(g_sq + b * NP + m0 + ty * 8);
        *(float4*)(sqr + 4) = *(const float4*)(g_sq + b * NP + m0 + ty * 8 + 4);
#pragma unroll
        for (int r = 0; r < 8; r++) {
            float v[8];
#pragma unroll
            for (int c = 0; c < 8; c++) {
                float w = slots[s2 * 65 + r * 8 + ((c + s2) & 7)];
                v[c] = fmaxf(fmaf(w, -2.f, sqn[c] + sqr[r]), 0.f);
            }
            float* op = g_key + ((size_t)(b * NP + m0 + ty * 8 + r)) * NP + n0 + tx * 8;
            *(float4*)op       = *(float4*)v;
            *(float4*)(op + 4) = *(float4*)(v + 4);
        }
    }
}

// Two-round 8-bit radix select of the 20 smallest keys per row. Keys are
// positive floats -> raw bits are unsigned-sortable. Exact, stable-argsort
// tie-break. Self excluded via u = 0xFFFFFFFF.
#define CAND_MAX 256
__global__ __launch_bounds__(256) void k_select() {
    int gp = blockIdx.x;                       // b*NP + n
    int n  = gp & (NP - 1);
    const float4* row4 = (const float4*)(g_key + (size_t)gp * NP);
    __shared__ unsigned hist[256];
    __shared__ unsigned cand_u[CAND_MAX];
    __shared__ int      cand_m[CAND_MAX];
    __shared__ unsigned wsum[8];
    __shared__ int s_sel, s_cand, s_b1, s_c1, s_b2, s_c2;
    int t = threadIdx.x;
    int lane = t & 31;
    hist[t] = 0u;
    if (t == 0) { s_sel = 0; s_cand = 0; }
    __syncthreads();

    unsigned u[8];
    {
        float4 a = __ldcs(row4 + t * 2);
        float4 c = __ldcs(row4 + t * 2 + 1);
        float vals[8] = {a.x, a.y, a.z, a.w, c.x, c.y, c.z, c.w};
        int m0 = t * 8;
#pragma unroll
        for (int i = 0; i < 8; i++) {
            unsigned b32 = __float_as_uint(vals[i]);
            if (m0 + i == n) b32 = 0xFFFFFFFFu;
            u[i] = b32;
        }
    }
    // round-1 histogram on bits [31:24], warp-aggregated
#pragma unroll
    for (int i = 0; i < 8; i++) {
        unsigned bin = u[i] >> 24;
        unsigned peers = __match_any_sync(0xFFFFFFFFu, bin);
        if ((peers & ((1u << lane) - 1u)) == 0u)
            atomicAdd(&hist[bin], (unsigned)__popc(peers));
    }
    __syncthreads();
    // scan 1
    {
        unsigned cnt = hist[t];
        unsigned v = cnt;
#pragma unroll
        for (int d = 1; d < 32; d <<= 1) {
            unsigned o = __shfl_up_sync(0xFFFFFFFFu, v, d);
            if (lane >= d) v += o;
        }
        if (lane == 31) wsum[t >> 5] = v;
        __syncthreads();
        unsigned woff = 0;
        for (int w = 0; w < (t >> 5); w++) woff += wsum[w];
        unsigned incl = v + woff;
        unsigned excl = incl - cnt;
        if (excl < KNN && incl >= KNN) { s_b1 = t; s_c1 = (int)excl; }
    }
    __syncthreads();
    unsigned b1 = (unsigned)s_b1;
    int c1 = s_c1;
    hist[t] = 0u;
    __syncthreads();
    // round-2 histogram on bits [23:16] within bin b1
#pragma unroll
    for (int i = 0; i < 8; i++) {
        bool pred = (u[i] >> 24) == b1;
        unsigned act = __ballot_sync(0xFFFFFFFFu, pred);
        if (pred) {
            unsigned bin = (u[i] >> 16) & 255u;
            unsigned peers = __match_any_sync(act, bin);
            if ((peers & ((1u << lane) - 1u)) == 0u)
                atomicAdd(&hist[bin], (unsigned)__popc(peers));
        }
    }
    __syncthreads();
    int need2 = KNN - c1;
    // scan 2
    {
        unsigned cnt = hist[t];
        unsigned v = cnt;
#pragma unroll
        for (int d = 1; d < 32; d <<= 1) {
            unsigned o = __shfl_up_sync(0xFFFFFFFFu, v, d);
            if (lane >= d) v += o;
        }
        if (lane == 31) wsum[t >> 5] = v;
        __syncthreads();
        unsigned woff = 0;
        for (int w = 0; w < (t >> 5); w++) woff += wsum[w];
        unsigned incl = v + woff;
        unsigned excl = incl - cnt;
        if ((int)excl < need2 && (int)incl >= need2) { s_b2 = t; s_c2 = (int)excl; }
    }
    __syncthreads();
    unsigned b2 = (unsigned)s_b2;
    int c2 = s_c2;
    unsigned Tsel  = (b1 << 24) | (b2 << 16);   // u < Tsel  <=> definitely top
    unsigned Tcand = (b1 << 8) | b2;            // (u>>16)==Tcand <=> boundary bin
    int* out = g_idx + gp * KNN;
#pragma unroll
    for (int i = 0; i < 8; i++) {
        unsigned ui = u[i];
        if (ui < Tsel) {
            out[atomicAdd(&s_sel, 1)] = t * 8 + i;
        } else if ((ui >> 16) == Tcand) {
            int c = atomicAdd(&s_cand, 1);
            if (c < CAND_MAX) { cand_u[c] = ui; cand_m[c] = t * 8 + i; }
        }
    }
    __syncthreads();
    int need3 = need2 - c2;
    int cc = min(s_cand, CAND_MAX);
    for (int c = t; c < cc; c += 256) {
        unsigned uc = cand_u[c];
        int mc = cand_m[c];
        int rank = 0;
        for (int j = 0; j < cc; j++) {
            unsigned uj = cand_u[j];
            rank += (uj < uc || (uj == uc && cand_m[j] < mc)) ? 1 : 0;
        }
        if (rank < need3) out[atomicAdd(&s_sel, 1)] = mc;
    }
}

// P[b,n,:] = A^T x + bias ; Q[b,n,:] = C^T x   via pre-transposed g_A/g_C,
// packed f32x2 over point pairs.
__global__ __launch_bounds__(256, 2) void k_pq(const float* __restrict__ x,
                                               const float* __restrict__ bias) {
    extern __shared__ float sm[];
    float* Ash = sm;                 // [64][128]
    float* Csh = sm + 8192;          // [64][128]
    float* xs  = sm + 16384;         // [64][64]
    int b  = blockIdx.y;
    int n0 = blockIdx.x * 64;
    int tid = threadIdx.x;
#pragma unroll
    for (int i = 0; i < 8; i++) {
        int id = (tid + 256 * i) * 4;       // 0..8191 floats, coalesced
        *(float4*)(Ash + id) = *(const float4*)(g_A + id);
        *(float4*)(Csh + id) = *(const float4*)(g_C + id);
    }
#pragma unroll
    for (int i = 0; i < 4; i++) {
        int id = tid + 256 * i;
        int f = id >> 4, c = (id & 15) * 4;
        *(float4*)(xs + f * 64 + c) = *(const float4*)(x + ((size_t)b * FIN + f) * NP + n0 + c);
    }
    __syncthreads();
    int tn = tid & 7, to = tid >> 3;
    int o0 = to * 4, nl0 = tn * 8;
    u64 accP[4][4], accQ[4][4];
    float4 bi = *(const float4*)(bias + o0);
    float bia[4] = {bi.x, bi.y, bi.z, bi.w};
#pragma unroll
    for (int i = 0; i < 4; i++) {
        u64 bd = dupf(bia[i]);
#pragma unroll
        for (int j = 0; j < 4; j++) { accP[i][j] = bd; accQ[i][j] = 0ull; }
    }
#pragma unroll 4
    for (int f = 0; f < 64; f++) {
        float4 a4 = *(float4*)(Ash + f * 128 + o0);
        float4 c4 = *(float4*)(Csh + f * 128 + o0);
        ulonglong2 x0 = *(ulonglong2*)(xs + f * 64 + nl0);
        ulonglong2 x1 = *(ulonglong2*)(xs + f * 64 + nl0 + 4);
        u64 xp[4] = {x0.x, x0.y, x1.x, x1.y};
        float aa[4] = {a4.x, a4.y, a4.z, a4.w};
        float cc[4] = {c4.x, c4.y, c4.z, c4.w};
#pragma unroll
        for (int i = 0; i < 4; i++) {
            u64 ad = dupf(aa[i]), cd = dupf(cc[i]);
#pragma unroll
            for (int j = 0; j < 4; j++) {
                accP[i][j] = fma2(ad, xp[j], accP[i][j]);
                accQ[i][j] = fma2(cd, xp[j], accQ[i][j]);
            }
        }
    }
#pragma unroll
    for (int jj = 0; jj < 8; jj++) {
        int j = jj >> 1, h = jj & 1;
        float pv[4], qv[4];
#pragma unroll
        for (int i = 0; i < 4; i++) {
            float2 p2 = unpack2(accP[i][j]); pv[i] = h ? p2.y : p2.x;
            float2 q2 = unpack2(accQ[i][j]); qv[i] = h ? q2.y : q2.x;
        }
        size_t base = (size_t)(b * NP + n0 + nl0 + jj) * FOUT + o0;
        *(float4*)(g_P + base) = make_float4(pv[0], pv[1], pv[2], pv[3]);
        *(float4*)(g_Q + base) = make_float4(qv[0], qv[1], qv[2], qv[3]);
    }
}

// Per (b,n): gather K neighbor Q columns; ymax/ymin = P + max/min_k Q;
// accumulate per-channel sum(y), sum(y^2) over edges.
__global__ __launch_bounds__(256) void k_edge() {
    __shared__ float bs1[FOUT], bs2[FOUT];
    int tid = threadIdx.x;
    int w = tid >> 5, lane = tid & 31;
    if (tid < FOUT) { bs1[tid] = 0.f; bs2[tid] = 0.f; }
    __syncthreads();
    int gp = blockIdx.x * 8 + w;
    int b  = gp >> 11;
    size_t pbase = (size_t)gp * FOUT + lane * 4;
    float4 p = *(const float4*)(g_P + pbase);
    const int* idx = g_idx + gp * KNN;
    const float INF = __int_as_float(0x7f800000);
    float4 qmax = make_float4(-INF, -INF, -INF, -INF);
    float4 qmin = make_float4(INF, INF, INF, INF);
    float4 s  = make_float4(0.f, 0.f, 0.f, 0.f);
    float4 s2 = make_float4(0.f, 0.f, 0.f, 0.f);
#pragma unroll 4
    for (int k = 0; k < KNN; k++) {
        int m = __ldg(idx + k);
        float4 q = *(const float4*)(g_Q + ((size_t)(b * NP + m)) * FOUT + lane * 4);
        qmax.x = fmaxf(qmax.x, q.x); qmax.y = fmaxf(qmax.y, q.y);
        qmax.z = fmaxf(qmax.z, q.z); qmax.w = fmaxf(qmax.w, q.w);
        qmin.x = fminf(qmin.x, q.x); qmin.y = fminf(qmin.y, q.y);
        qmin.z = fminf(qmin.z, q.z); qmin.w = fminf(qmin.w, q.w);
        s.x += q.x; s.y += q.y; s.z += q.z; s.w += q.w;
        s2.x = fmaf(q.x, q.x, s2.x); s2.y = fmaf(q.y, q.y, s2.y);
        s2.z = fmaf(q.z, q.z, s2.z); s2.w = fmaf(q.w, q.w, s2.w);
    }
    float4 ymax = make_float4(p.x + qmax.x, p.y + qmax.y, p.z + qmax.z, p.w + qmax.w);
    float4 ymin = make_float4(p.x + qmin.x, p.y + qmin.y, p.z + qmin.z, p.w + qmin.w);
    *(float4*)(g_ymax + pbase) = ymax;
    *(float4*)(g_ymin + pbase) = ymin;
    float s1a[4], ssa[4];
    float pp[4] = {p.x, p.y, p.z, p.w};
    float sa[4] = {s.x, s.y, s.z, s.w};
    float s2a[4] = {s2.x, s2.y, s2.z, s2.w};
#pragma unroll
    for (int i = 0; i < 4; i++) {
        s1a[i] = fmaf((float)KNN, pp[i], sa[i]);
        ssa[i] = fmaf(pp[i], fmaf((float)KNN, pp[i], 2.f * sa[i]), s2a[i]);
    }
#pragma unroll
    for (int i = 0; i < 4; i++) {
        atomicAdd(&bs1[lane * 4 + i], s1a[i]);
        atomicAdd(&bs2[lane * 4 + i], ssa[i]);
    }
    __syncthreads();
    if (tid < FOUT) {
        atomicAdd(&g_S1[tid], bs1[tid]);
        atomicAdd(&g_S2[tid], bs2[tid]);
    }
}

__global__ void k_stats(const float* __restrict__ gamma, const float* __restrict__ beta) {
    int o = threadIdx.x;
    const float inv = 1.f / (float)EDGES;
    float m   = g_S1[o] * inv;
    float var = fmaf(-m, m, g_S2[o] * inv);
    float sc  = gamma[o] * rsqrtf(var + 1e-5f);
    g_scale[o] = sc;
    g_shift[o] = fmaf(-m, sc, beta[o]);
}

// out[b,o,n] = relu(scale*(scale>=0 ? ymax : ymin) + shift), transposed write.
__global__ __launch_bounds__(256) void k_out(float* __restrict__ out) {
    __shared__ float sh[FOUT * 36];
    __shared__ float ssc[FOUT], ssf[FOUT];
    int b  = blockIdx.y;
    int n0 = blockIdx.x * 32;
    int tid = threadIdx.x;
    if (tid < FOUT) { ssc[tid] = g_scale[tid]; ssf[tid] = g_shift[tid]; }
    __syncthreads();
    int o  = tid & 127;
    int nh = tid >> 7;
    float sc = ssc[o], sf = ssf[o];
#pragma unroll
    for (int it = 0; it < 16; it++) {
        int nl = it * 2 + nh;
        size_t base = ((size_t)(b * NP + n0 + nl)) * FOUT + o;
        float vmax = g_ymax[base], vmin = g_ymin[base];
        float v = (sc >= 0.f) ? vmax : vmin;
        sh[o * 36 + nl] = fmaxf(fmaf(sc, v, sf), 0.f);
    }
    __syncthreads();
    int ow = tid >> 1;
    int h  = tid & 1;
    float* dst = out + ((size_t)(b * FOUT + ow)) * NP + n0 + h * 16;
    const float* src = sh + ow * 36 + h * 16;
#pragma unroll
    for (int j = 0; j < 4; j++)
        *(float4*)(dst + j * 4) = *(const float4*)(src + j * 4);
}

// ---------------- launch ----------------------------------------------------
extern "C" void kernel_launch(void* const* d_in, const int* in_sizes, int n_in,
                              void* d_out, int out_size) {
    const float* x     = (const float*)d_in[0];
    const float* W     = (const float*)d_in[1];
    const float* bias  = (const float*)d_in[2];
    const float* gamma = (const float*)d_in[3];
    const float* beta  = (const float*)d_in[4];
    float* out = (float*)d_out;

    const int GRAM_SMEM = 256 * 65 * 4;   // 66560 B (>= 2*64*128*4 = 65536)
    const int PQ_SMEM   = (2 * 64 * 128 + 64 * 64) * 4;  // 81920 B
    cudaFuncSetAttribute(k_gram, cudaFuncAttributeMaxDynamicSharedMemorySize, GRAM_SMEM);
    cudaFuncSetAttribute(k_pq,   cudaFuncAttributeMaxDynamicSharedMemorySize, PQ_SMEM);

    k_zero<<<1, 128>>>();
    k_prep<<<32, 256>>>(W);               // exactly FIN*FOUT = 8192 threads
    k_sq<<<NPTS / 256, 256>>>(x);
    k_gram<<<dim3(136, 1, NB), 256, GRAM_SMEM>>>(x);
    k_select<<<NPTS, 256>>>();
    k_pq<<<dim3(NP / 64, NB), 256, PQ_SMEM>>>(x, bias);
    k_edge<<<NPTS / 8, 256>>>();
    k_stats<<<1, 128>>>(gamma, beta);
    k_out<<<dim3(NP / 32, NB), 256>>>(out);
}

// round 11
// speedup vs baseline: 1.3290x; 1.3290x over previous
#include <cuda_runtime.h>
#include <cstdint>

#define NB   16
#define FIN  64
#define FOUT 128
#define NP   2048
#define KNN  20
#define NPTS (NB * NP)            /* 32768 */
#define EDGES (NPTS * KNN)        /* 655360 */

typedef unsigned long long u64;

// ---------------- scratch (device globals: no allocations allowed) ----------
__device__ float g_sq[NPTS];
__device__ float g_key[(size_t)NPTS * NP];   // 256 MB
__device__ int   g_idx[NPTS * KNN];
__device__ float g_A[FIN * FOUT];            // (W1-W2)^T  [f][o]
__device__ float g_C[FIN * FOUT];            // W2^T       [f][o]
__device__ float g_P[NPTS * FOUT];
__device__ float g_Q[NPTS * FOUT];
__device__ float g_ymax[NPTS * FOUT];
__device__ float g_ymin[NPTS * FOUT];
__device__ float g_S1[FOUT];
__device__ float g_S2[FOUT];
__device__ float g_scale[FOUT];
__device__ float g_shift[FOUT];

// ---------------- f32x2 helpers (Blackwell packed fp32 FMA) -----------------
__device__ __forceinline__ u64 fma2(u64 a, u64 b, u64 c) {
    u64 d;
    asm("fma.rn.f32x2 %0, %1, %2, %3;" : "=l"(d) : "l"(a), "l"(b), "l"(c));
    return d;
}
__device__ __forceinline__ u64 dupf(float a) {
    u64 d;
    unsigned u = __float_as_uint(a);
    asm("mov.b64 %0, {%1, %1};" : "=l"(d) : "r"(u));
    return d;
}
__device__ __forceinline__ float2 unpack2(u64 d) {
    unsigned lo, hi;
    asm("mov.b64 {%0, %1}, %2;" : "=r"(lo), "=r"(hi) : "l"(d));
    return make_float2(__uint_as_float(lo), __uint_as_float(hi));
}

// ---------------- kernels ---------------------------------------------------

__global__ void k_zero() {
    int t = threadIdx.x;
    if (t < FOUT) { g_S1[t] = 0.f; g_S2[t] = 0.f; }
}

// sq[b,n] = sum_f x^2
__global__ void k_sq(const float* __restrict__ x) {
    int gp = blockIdx.x * blockDim.x + threadIdx.x;
    if (gp >= NPTS) return;
    int b = gp >> 11, n = gp & (NP - 1);
    const float* p = x + (size_t)b * FIN * NP + n;
    float s = 0.f;
#pragma unroll
    for (int f = 0; f < FIN; f++) { float v = p[(size_t)f * NP]; s = fmaf(v, v, s); }
    g_sq[gp] = s;
}

// Transpose weights: g_A[f][o] = W[o][f]-W[o][64+f], g_C[f][o] = W[o][64+f]
__global__ void k_prep(const float* __restrict__ W) {
    int id = blockIdx.x * 256 + threadIdx.x;   // 0..8191
    if (id >= FIN * FOUT) return;
    int f = id >> 7, o = id & 127;
    float w1 = W[o * 128 + f], w2 = W[o * 128 + 64 + f];
    g_A[f * 128 + o] = w1 - w2;
    g_C[f * 128 + o] = w2;
}

// ===== EXACT R6 k_gram: symmetric lower-triangle tiles, key = sq[m]-2G =====
__global__ __launch_bounds__(256, 2) void k_gram(const float* __restrict__ x) {
    extern __shared__ float sm[];
    float* As = sm;               // [64][128]
    float* Bs = sm + 64 * 128;    // [64][128]
    int b = blockIdx.z;
    int kk = blockIdx.x;
    int ti = (int)((sqrtf(8.f * kk + 1.f) - 1.f) * 0.5f);
    while ((ti + 1) * (ti + 2) / 2 <= kk) ti++;
    while (ti * (ti + 1) / 2 > kk) ti--;
    int tj = kk - ti * (ti + 1) / 2;
    int n0 = ti * 128;            // rows
    int m0 = tj * 128;            // cols
    int tid = threadIdx.x;
    const float* xb = x + (size_t)b * FIN * NP;
#pragma unroll
    for (int i = 0; i < 8; i++) {
        int flat = (tid + 256 * i) * 4;
        int k = flat >> 7;
        int c = flat & 127;
        *(float4*)(As + k * 128 + c) = *(const float4*)(xb + (size_t)k * NP + n0 + c);
        *(float4*)(Bs + k * 128 + c) = *(const float4*)(xb + (size_t)k * NP + m0 + c);
    }
    __syncthreads();
    int tx = tid & 15, ty = tid >> 4;
    u64 acc[8][4];
#pragma unroll
    for (int i = 0; i < 8; i++)
#pragma unroll
        for (int j = 0; j < 4; j++) acc[i][j] = 0ull;

#pragma unroll 4
    for (int k = 0; k < 64; k++) {
        float4 a0 = *(float4*)(As + k * 128 + ty * 8);
        float4 a1 = *(float4*)(As + k * 128 + ty * 8 + 4);
        ulonglong2 bv0 = *(ulonglong2*)(Bs + k * 128 + tx * 8);
        ulonglong2 bv1 = *(ulonglong2*)(Bs + k * 128 + tx * 8 + 4);
        float av[8] = {a0.x, a0.y, a0.z, a0.w, a1.x, a1.y, a1.z, a1.w};
        u64 bv[4] = {bv0.x, bv0.y, bv1.x, bv1.y};
#pragma unroll
        for (int i = 0; i < 8; i++) {
            u64 ad = dupf(av[i]);
#pragma unroll
            for (int j = 0; j < 4; j++) acc[i][j] = fma2(ad, bv[j], acc[i][j]);
        }
    }
    float gf[8][8];
#pragma unroll
    for (int i = 0; i < 8; i++)
#pragma unroll
        for (int j = 0; j < 4; j++) {
            float2 p = unpack2(acc[i][j]);
            gf[i][2 * j] = p.x; gf[i][2 * j + 1] = p.y;
        }
    // direct tile
    {
        float sqm[8];
        *(float4*)sqm       = *(const float4*)(g_sq + b * NP + m0 + tx * 8);
        *(float4*)(sqm + 4) = *(const float4*)(g_sq + b * NP + m0 + tx * 8 + 4);
#pragma unroll
        for (int i = 0; i < 8; i++) {
            float v[8];
#pragma unroll
            for (int k = 0; k < 8; k++) v[k] = fmaf(gf[i][k], -2.f, sqm[k]);
            float* op = g_key + ((size_t)(b * NP + n0 + ty * 8 + i)) * NP + m0 + tx * 8;
            *(float4*)op       = *(float4*)v;
            *(float4*)(op + 4) = *(float4*)(v + 4);
        }
    }
    // transposed tile (off-diagonal only)
    if (ti != tj) {
        __syncthreads();
        int s = tid;
        float* slots = sm;
#pragma unroll
        for (int k = 0; k < 8; k++)
#pragma unroll
            for (int i = 0; i < 8; i++)
                slots[s * 65 + k * 8 + ((i + s) & 7)] = gf[i][k];
        __syncthreads();
        int s2 = ((tid & 15) << 4) | (tid >> 4);
        float sqn[8];
        *(float4*)sqn       = *(const float4*)(g_sq + b * NP + n0 + tx * 8);
        *(float4*)(sqn + 4) = *(const float4*)(g_sq + b * NP + n0 + tx * 8 + 4);
#pragma unroll
        for (int r = 0; r < 8; r++) {
            float v[8];
#pragma unroll
            for (int c = 0; c < 8; c++) {
                float w = slots[s2 * 65 + r * 8 + ((c + s2) & 7)];
                v[c] = fmaf(w, -2.f, sqn[c]);
            }
            float* op = g_key + ((size_t)(b * NP + m0 + ty * 8 + r)) * NP + n0 + tx * 8;
            *(float4*)op       = *(float4*)v;
            *(float4*)(op + 4) = *(float4*)(v + 4);
        }
    }
}

// ===== EXACT R6 k_select: sortable transform + two-round radix ==============
#define CAND_MAX 256
__global__ __launch_bounds__(256) void k_select() {
    int gp = blockIdx.x;                       // b*NP + n
    int n  = gp & (NP - 1);
    const float4* row4 = (const float4*)(g_key + (size_t)gp * NP);
    __shared__ unsigned hist[256];
    __shared__ unsigned cand_u[CAND_MAX];
    __shared__ int      cand_m[CAND_MAX];
    __shared__ unsigned wsum[8];
    __shared__ int s_sel, s_cand, s_b1, s_c1, s_b2, s_c2;
    int t = threadIdx.x;
    int lane = t & 31;
    hist[t] = 0u;
    if (t == 0) { s_sel = 0; s_cand = 0; }
    __syncthreads();

    unsigned u[8];
    {
        float4 a = __ldcs(row4 + t * 2);
        float4 c = __ldcs(row4 + t * 2 + 1);
        float vals[8] = {a.x, a.y, a.z, a.w, c.x, c.y, c.z, c.w};
        int m0 = t * 8;
#pragma unroll
        for (int i = 0; i < 8; i++) {
            unsigned b32 = __float_as_uint(vals[i]);
            b32 = ((int)b32 < 0) ? ~b32 : (b32 | 0x80000000u);
            if (m0 + i == n) b32 = 0xFFFFFFFFu;
            u[i] = b32;
        }
    }
    // round-1 histogram on bits [31:24], warp-aggregated
#pragma unroll
    for (int i = 0; i < 8; i++) {
        unsigned bin = u[i] >> 24;
        unsigned peers = __match_any_sync(0xFFFFFFFFu, bin);
        if ((peers & ((1u << lane) - 1u)) == 0u)
            atomicAdd(&hist[bin], (unsigned)__popc(peers));
    }
    __syncthreads();
    // scan 1
    {
        unsigned cnt = hist[t];
        unsigned v = cnt;
#pragma unroll
        for (int d = 1; d < 32; d <<= 1) {
            unsigned o = __shfl_up_sync(0xFFFFFFFFu, v, d);
            if (lane >= d) v += o;
        }
        if (lane == 31) wsum[t >> 5] = v;
        __syncthreads();
        unsigned woff = 0;
        for (int w = 0; w < (t >> 5); w++) woff += wsum[w];
        unsigned incl = v + woff;
        unsigned excl = incl - cnt;
        if (excl < KNN && incl >= KNN) { s_b1 = t; s_c1 = (int)excl; }
    }
    __syncthreads();
    unsigned b1 = (unsigned)s_b1;
    int c1 = s_c1;
    hist[t] = 0u;
    __syncthreads();
    // round-2 histogram on bits [23:16] within bin b1
#pragma unroll
    for (int i = 0; i < 8; i++) {
        bool pred = (u[i] >> 24) == b1;
        unsigned act = __ballot_sync(0xFFFFFFFFu, pred);
        if (pred) {
            unsigned bin = (u[i] >> 16) & 255u;
            unsigned peers = __match_any_sync(act, bin);
            if ((peers & ((1u << lane) - 1u)) == 0u)
                atomicAdd(&hist[bin], (unsigned)__popc(peers));
        }
    }
    __syncthreads();
    int need2 = KNN - c1;
    // scan 2
    {
        unsigned cnt = hist[t];
        unsigned v = cnt;
#pragma unroll
        for (int d = 1; d < 32; d <<= 1) {
            unsigned o = __shfl_up_sync(0xFFFFFFFFu, v, d);
            if (lane >= d) v += o;
        }
        if (lane == 31) wsum[t >> 5] = v;
        __syncthreads();
        unsigned woff = 0;
        for (int w = 0; w < (t >> 5); w++) woff += wsum[w];
        unsigned incl = v + woff;
        unsigned excl = incl - cnt;
        if ((int)excl < need2 && (int)incl >= need2) { s_b2 = t; s_c2 = (int)excl; }
    }
    __syncthreads();
    unsigned b2 = (unsigned)s_b2;
    int c2 = s_c2;
    int* out = g_idx + gp * KNN;
#pragma unroll
    for (int i = 0; i < 8; i++) {
        unsigned d1 = u[i] >> 24;
        if (d1 < b1) {
            out[atomicAdd(&s_sel, 1)] = t * 8 + i;
        } else if (d1 == b1) {
            unsigned d2 = (u[i] >> 16) & 255u;
            if (d2 < b2) {
                out[atomicAdd(&s_sel, 1)] = t * 8 + i;
            } else if (d2 == b2) {
                int c = atomicAdd(&s_cand, 1);
                if (c < CAND_MAX) { cand_u[c] = u[i]; cand_m[c] = t * 8 + i; }
            }
        }
    }
    __syncthreads();
    int need3 = need2 - c2;
    int cc = min(s_cand, CAND_MAX);
    for (int c = t; c < cc; c += 256) {
        unsigned uc = cand_u[c];
        int mc = cand_m[c];
        int rank = 0;
        for (int j = 0; j < cc; j++) {
            unsigned uj = cand_u[j];
            rank += (uj < uc || (uj == uc && cand_m[j] < mc)) ? 1 : 0;
        }
        if (rank < need3) out[atomicAdd(&s_sel, 1)] = mc;
    }
}

// ===== NEW k_pq (under test): pre-transposed weights, packed f32x2 ==========
__global__ __launch_bounds__(256, 2) void k_pq(const float* __restrict__ x,
                                               const float* __restrict__ bias) {
    extern __shared__ float sm[];
    float* Ash = sm;                 // [64][128]
    float* Csh = sm + 8192;          // [64][128]
    float* xs  = sm + 16384;         // [64][64]
    int b  = blockIdx.y;
    int n0 = blockIdx.x * 64;
    int tid = threadIdx.x;
#pragma unroll
    for (int i = 0; i < 8; i++) {
        int id = (tid + 256 * i) * 4;       // 0..8191 floats, coalesced
        *(float4*)(Ash + id) = *(const float4*)(g_A + id);
        *(float4*)(Csh + id) = *(const float4*)(g_C + id);
    }
#pragma unroll
    for (int i = 0; i < 4; i++) {
        int id = tid + 256 * i;
        int f = id >> 4, c = (id & 15) * 4;
        *(float4*)(xs + f * 64 + c) = *(const float4*)(x + ((size_t)b * FIN + f) * NP + n0 + c);
    }
    __syncthreads();
    int tn = tid & 7, to = tid >> 3;
    int o0 = to * 4, nl0 = tn * 8;
    u64 accP[4][4], accQ[4][4];
    float4 bi = *(const float4*)(bias + o0);
    float bia[4] = {bi.x, bi.y, bi.z, bi.w};
#pragma unroll
    for (int i = 0; i < 4; i++) {
        u64 bd = dupf(bia[i]);
#pragma unroll
        for (int j = 0; j < 4; j++) { accP[i][j] = bd; accQ[i][j] = 0ull; }
    }
#pragma unroll 4
    for (int f = 0; f < 64; f++) {
        float4 a4 = *(float4*)(Ash + f * 128 + o0);
        float4 c4 = *(float4*)(Csh + f * 128 + o0);
        ulonglong2 x0 = *(ulonglong2*)(xs + f * 64 + nl0);
        ulonglong2 x1 = *(ulonglong2*)(xs + f * 64 + nl0 + 4);
        u64 xp[4] = {x0.x, x0.y, x1.x, x1.y};
        float aa[4] = {a4.x, a4.y, a4.z, a4.w};
        float cc[4] = {c4.x, c4.y, c4.z, c4.w};
#pragma unroll
        for (int i = 0; i < 4; i++) {
            u64 ad = dupf(aa[i]), cd = dupf(cc[i]);
#pragma unroll
            for (int j = 0; j < 4; j++) {
                accP[i][j] = fma2(ad, xp[j], accP[i][j]);
                accQ[i][j] = fma2(cd, xp[j], accQ[i][j]);
            }
        }
    }
#pragma unroll
    for (int jj = 0; jj < 8; jj++) {
        int j = jj >> 1, h = jj & 1;
        float pv[4], qv[4];
#pragma unroll
        for (int i = 0; i < 4; i++) {
            float2 p2 = unpack2(accP[i][j]); pv[i] = h ? p2.y : p2.x;
            float2 q2 = unpack2(accQ[i][j]); qv[i] = h ? q2.y : q2.x;
        }
        size_t base = (size_t)(b * NP + n0 + nl0 + jj) * FOUT + o0;
        *(float4*)(g_P + base) = make_float4(pv[0], pv[1], pv[2], pv[3]);
        *(float4*)(g_Q + base) = make_float4(qv[0], qv[1], qv[2], qv[3]);
    }
}

// Per (b,n): gather K neighbor Q columns; ymax/ymin = P + max/min_k Q;
// accumulate per-channel sum(y), sum(y^2) over edges.
__global__ __launch_bounds__(256) void k_edge() {
    __shared__ float bs1[FOUT], bs2[FOUT];
    int tid = threadIdx.x;
    int w = tid >> 5, lane = tid & 31;
    if (tid < FOUT) { bs1[tid] = 0.f; bs2[tid] = 0.f; }
    __syncthreads();
    int gp = blockIdx.x * 8 + w;
    int b  = gp >> 11;
    size_t pbase = (size_t)gp * FOUT + lane * 4;
    float4 p = *(const float4*)(g_P + pbase);
    const int* idx = g_idx + gp * KNN;
    const float INF = __int_as_float(0x7f800000);
    float4 qmax = make_float4(-INF, -INF, -INF, -INF);
    float4 qmin = make_float4(INF, INF, INF, INF);
    float4 s  = make_float4(0.f, 0.f, 0.f, 0.f);
    float4 s2 = make_float4(0.f, 0.f, 0.f, 0.f);
#pragma unroll 4
    for (int k = 0; k < KNN; k++) {
        int m = __ldg(idx + k);
        float4 q = *(const float4*)(g_Q + ((size_t)(b * NP + m)) * FOUT + lane * 4);
        qmax.x = fmaxf(qmax.x, q.x); qmax.y = fmaxf(qmax.y, q.y);
        qmax.z = fmaxf(qmax.z, q.z); qmax.w = fmaxf(qmax.w, q.w);
        qmin.x = fminf(qmin.x, q.x); qmin.y = fminf(qmin.y, q.y);
        qmin.z = fminf(qmin.z, q.z); qmin.w = fminf(qmin.w, q.w);
        s.x += q.x; s.y += q.y; s.z += q.z; s.w += q.w;
        s2.x = fmaf(q.x, q.x, s2.x); s2.y = fmaf(q.y, q.y, s2.y);
        s2.z = fmaf(q.z, q.z, s2.z); s2.w = fmaf(q.w, q.w, s2.w);
    }
    float4 ymax = make_float4(p.x + qmax.x, p.y + qmax.y, p.z + qmax.z, p.w + qmax.w);
    float4 ymin = make_float4(p.x + qmin.x, p.y + qmin.y, p.z + qmin.z, p.w + qmin.w);
    *(float4*)(g_ymax + pbase) = ymax;
    *(float4*)(g_ymin + pbase) = ymin;
    float s1a[4], ssa[4];
    float pp[4] = {p.x, p.y, p.z, p.w};
    float sa[4] = {s.x, s.y, s.z, s.w};
    float s2a[4] = {s2.x, s2.y, s2.z, s2.w};
#pragma unroll
    for (int i = 0; i < 4; i++) {
        s1a[i] = fmaf((float)KNN, pp[i], sa[i]);
        ssa[i] = fmaf(pp[i], fmaf((float)KNN, pp[i], 2.f * sa[i]), s2a[i]);
    }
#pragma unroll
    for (int i = 0; i < 4; i++) {
        atomicAdd(&bs1[lane * 4 + i], s1a[i]);
        atomicAdd(&bs2[lane * 4 + i], ssa[i]);
    }
    __syncthreads();
    if (tid < FOUT) {
        atomicAdd(&g_S1[tid], bs1[tid]);
        atomicAdd(&g_S2[tid], bs2[tid]);
    }
}

__global__ void k_stats(const float* __restrict__ gamma, const float* __restrict__ beta) {
    int o = threadIdx.x;
    const float inv = 1.f / (float)EDGES;
    float m   = g_S1[o] * inv;
    float var = fmaf(-m, m, g_S2[o] * inv);
    float sc  = gamma[o] * rsqrtf(var + 1e-5f);
    g_scale[o] = sc;
    g_shift[o] = fmaf(-m, sc, beta[o]);
}

// out[b,o,n] = relu(scale*(scale>=0 ? ymax : ymin) + shift), transposed write.
__global__ __launch_bounds__(256) void k_out(float* __restrict__ out) {
    __shared__ float sh[FOUT * 36];
    __shared__ float ssc[FOUT], ssf[FOUT];
    int b  = blockIdx.y;
    int n0 = blockIdx.x * 32;
    int tid = threadIdx.x;
    if (tid < FOUT) { ssc[tid] = g_scale[tid]; ssf[tid] = g_shift[tid]; }
    __syncthreads();
    int o  = tid & 127;
    int nh = tid >> 7;
    float sc = ssc[o], sf = ssf[o];
#pragma unroll
    for (int it = 0; it < 16; it++) {
        int nl = it * 2 + nh;
        size_t base = ((size_t)(b * NP + n0 + nl)) * FOUT + o;
        float vmax = g_ymax[base], vmin = g_ymin[base];
        float v = (sc >= 0.f) ? vmax : vmin;
        sh[o * 36 + nl] = fmaxf(fmaf(sc, v, sf), 0.f);
    }
    __syncthreads();
    int ow = tid >> 1;
    int h  = tid & 1;
    float* dst = out + ((size_t)(b * FOUT + ow)) * NP + n0 + h * 16;
    const float* src = sh + ow * 36 + h * 16;
#pragma unroll
    for (int j = 0; j < 4; j++)
        *(float4*)(dst + j * 4) = *(const float4*)(src + j * 4);
}

// ---------------- launch ----------------------------------------------------
extern "C" void kernel_launch(void* const* d_in, const int* in_sizes, int n_in,
                              void* d_out, int out_size) {
    const float* x     = (const float*)d_in[0];
    const float* W     = (const float*)d_in[1];
    const float* bias  = (const float*)d_in[2];
    const float* gamma = (const float*)d_in[3];
    const float* beta  = (const float*)d_in[4];
    float* out = (float*)d_out;

    const int GRAM_SMEM = 256 * 65 * 4;   // 66560 B
    const int PQ_SMEM   = (2 * 64 * 128 + 64 * 64) * 4;  // 81920 B
    cudaFuncSetAttribute(k_gram, cudaFuncAttributeMaxDynamicSharedMemorySize, GRAM_SMEM);
    cudaFuncSetAttribute(k_pq,   cudaFuncAttributeMaxDynamicSharedMemorySize, PQ_SMEM);

    k_zero<<<1, 128>>>();
    k_prep<<<32, 256>>>(W);
    k_sq<<<NPTS / 256, 256>>>(x);
    k_gram<<<dim3(136, 1, NB), 256, GRAM_SMEM>>>(x);
    k_select<<<NPTS, 256>>>();
    k_pq<<<dim3(NP / 64, NB), 256, PQ_SMEM>>>(x, bias);
    k_edge<<<NPTS / 8, 256>>>();
    k_stats<<<1, 128>>>(gamma, beta);
    k_out<<<dim3(NP / 32, NB), 256>>>(out);
}